// round 2
// baseline (speedup 1.0000x reference)
#include <cuda_runtime.h>
#include <stdint.h>

// Problem constants (match reference setup)
#define NN 100000          // N_NODES
#define DIM 256            // DIM_ATTEN
#define DIM4 (DIM / 4)     // float4 per node row
#define HASH_BITS 22
#define HASH_SIZE (1u << HASH_BITS)   // 4,194,304 slots (32 MB)
#define HASH_MASK (HASH_SIZE - 1u)
#define EMPTY_KEY 0xFFFFFFFFFFFFFFFFULL

// Scratch (device globals — no dynamic allocation allowed)
__device__ unsigned long long g_hash[HASH_SIZE];
__device__ int g_in_deg[NN];
__device__ int g_out_deg[NN];

// ---------------------------------------------------------------------------
// Kernel 1: clear hash table + degree counters
// ---------------------------------------------------------------------------
__global__ void clear_kernel() {
    const unsigned tid = blockIdx.x * blockDim.x + threadIdx.x;
    const unsigned stride = gridDim.x * blockDim.x;
    // 16B vectorized clear of the hash table
    ulonglong2* h2 = reinterpret_cast<ulonglong2*>(g_hash);
    const unsigned n2 = HASH_SIZE / 2;
    for (unsigned i = tid; i < n2; i += stride) {
        h2[i] = make_ulonglong2(EMPTY_KEY, EMPTY_KEY);
    }
    for (unsigned i = tid; i < NN; i += stride) {
        g_in_deg[i] = 0;
        g_out_deg[i] = 0;
    }
}

// ---------------------------------------------------------------------------
// Kernel 2: dedup edges via open-addressing hash set; count degrees for
// unique pairs. edge_index is INT32 on device (JAX x64 disabled).
//   in_degree[src]  += 1 per unique (src,dst)
//   out_degree[dst] += 1 per unique (src,dst)
// ---------------------------------------------------------------------------
__device__ __forceinline__ unsigned long long mix64(unsigned long long h) {
    h ^= h >> 33;
    h *= 0xff51afd7ed558ccdULL;
    h ^= h >> 33;
    h *= 0xc4ceb9fe1a85ec53ULL;
    h ^= h >> 33;
    return h;
}

__global__ void edge_kernel(const int* __restrict__ edge_index, int n_edges) {
    const int e = blockIdx.x * blockDim.x + threadIdx.x;
    if (e >= n_edges) return;

    int s = edge_index[e];            // row 0: src
    int d = edge_index[e + n_edges];  // row 1: dst
    // defensive clamp (values are guaranteed [0, NN) by the generator)
    s = min(max(s, 0), NN - 1);
    d = min(max(d, 0), NN - 1);

    const unsigned long long key =
        (unsigned long long)s * (unsigned long long)NN + (unsigned long long)d;

    unsigned slot = (unsigned)mix64(key) & HASH_MASK;
    while (true) {
        unsigned long long prev = atomicCAS(&g_hash[slot], EMPTY_KEY, key);
        if (prev == EMPTY_KEY) {
            // first time this (src,dst) pair is seen
            atomicAdd(&g_in_deg[s], 1);
            atomicAdd(&g_out_deg[d], 1);
            return;
        }
        if (prev == key) return;  // duplicate edge — drop
        slot = (slot + 1) & HASH_MASK;
    }
}

// ---------------------------------------------------------------------------
// Kernel 3: node_feature = x + in_tbl[in_deg] + out_tbl[out_deg]
// Table row 0 is all-zero in the reference, so padding_idx=0 is free.
// One thread per float4 (64 per node).
// ---------------------------------------------------------------------------
__global__ void fuse_kernel(const float4* __restrict__ x,
                            const float4* __restrict__ in_tbl,
                            const float4* __restrict__ out_tbl,
                            float4* __restrict__ out) {
    const unsigned tid = blockIdx.x * blockDim.x + threadIdx.x;
    if (tid >= (unsigned)NN * DIM4) return;

    const unsigned node = tid >> 6;     // /64
    const unsigned col  = tid & 63;

    int di = g_in_deg[node];            // broadcast within warp halves
    int dd = g_out_deg[node];
    di = min(max(di, 0), 511);
    dd = min(max(dd, 0), 511);

    const float4 xv = x[tid];
    const float4 a  = __ldg(&in_tbl[(unsigned)di * DIM4 + col]);
    const float4 b  = __ldg(&out_tbl[(unsigned)dd * DIM4 + col]);

    float4 r;
    r.x = xv.x + a.x + b.x;
    r.y = xv.y + a.y + b.y;
    r.z = xv.z + a.z + b.z;
    r.w = xv.w + a.w + b.w;
    out[tid] = r;
}

// Zero any tail of d_out beyond node_feature (attn_bias = 0)
__global__ void tail_zero_kernel(float* __restrict__ out, long long start, long long total) {
    long long i = start + (long long)(blockIdx.x * blockDim.x + threadIdx.x);
    if (i < total) out[i] = 0.0f;
}

// ---------------------------------------------------------------------------
// Launch
// Inputs (metadata order):
//   0: x                 [100000, 256] float32
//   1: edge_feature      [1600000, 128] float32 (zeros — unused)
//   2: edge_index        [2, 1600000] int32 (JAX x64 disabled)
//   3: in_degree_table   [512, 256] float32
//   4: out_degree_table  [512, 256] float32
// Output: node_feature   [100000, 256] float32 (+ possible attn_bias tail)
// ---------------------------------------------------------------------------
extern "C" void kernel_launch(void* const* d_in, const int* in_sizes, int n_in,
                              void* d_out, int out_size) {
    const float4* x        = (const float4*)d_in[0];
    const int* ei          = (const int*)d_in[2];
    const float4* in_tbl   = (const float4*)d_in[3];
    const float4* out_tbl  = (const float4*)d_in[4];
    float4* out            = (float4*)d_out;

    const int n_edges = in_sizes[2] / 2;

    // 1) clear scratch
    clear_kernel<<<2048, 256>>>();

    // 2) dedup + degree count
    edge_kernel<<<(n_edges + 255) / 256, 256>>>(ei, n_edges);

    // 3) fused gather-add (HBM-bound streaming kernel)
    const unsigned total4 = (unsigned)NN * DIM4;  // 6,400,000
    fuse_kernel<<<(total4 + 255) / 256, 256>>>(x, in_tbl, out_tbl, out);

    // 4) zero any tail (attn_bias scalar etc.)
    const long long nf_elems = (long long)NN * DIM;  // 25,600,000
    if ((long long)out_size > nf_elems) {
        const long long extra = (long long)out_size - nf_elems;
        tail_zero_kernel<<<(unsigned)((extra + 255) / 256), 256>>>(
            (float*)d_out, nf_elems, (long long)out_size);
    }
}

// round 3
// speedup vs baseline: 1.0037x; 1.0037x over previous
#include <cuda_runtime.h>
#include <stdint.h>

// Problem constants (match reference setup)
#define NN 100000          // N_NODES
#define DIM 256            // DIM_ATTEN
#define DIM4 (DIM / 4)     // float4 per node row
#define HASH_BITS 22
#define HASH_SIZE (1u << HASH_BITS)   // 4,194,304 slots x u32 = 16 MB
#define HASH_MASK (HASH_SIZE - 1u)

// Scratch (device globals — no dynamic allocation allowed)
__device__ unsigned int g_hash[HASH_SIZE];   // 0 = empty, else 32-bit fingerprint
__device__ int g_in_deg[NN];
__device__ int g_out_deg[NN];

// ---------------------------------------------------------------------------
// Kernel 1: clear hash table (16 MB) + degree counters (0.8 MB), vectorized.
// ---------------------------------------------------------------------------
__global__ void clear_kernel() {
    const unsigned tid = blockIdx.x * blockDim.x + threadIdx.x;
    const unsigned stride = gridDim.x * blockDim.x;
    uint4* h4 = reinterpret_cast<uint4*>(g_hash);
    const unsigned n4 = HASH_SIZE / 4;           // 1,048,576 uint4 stores
    const uint4 z = make_uint4(0u, 0u, 0u, 0u);
    for (unsigned i = tid; i < n4; i += stride) h4[i] = z;
    for (unsigned i = tid; i < NN; i += stride) {
        g_in_deg[i] = 0;
        g_out_deg[i] = 0;
    }
}

// ---------------------------------------------------------------------------
// Kernel 2: dedup edges via fingerprint hash set; count degrees for unique
// pairs. edge_index is INT32 on device (JAX x64 disabled). 2 edges/thread.
// ---------------------------------------------------------------------------
__device__ __forceinline__ unsigned long long mix64(unsigned long long h) {
    h ^= h >> 33;
    h *= 0xff51afd7ed558ccdULL;
    h ^= h >> 33;
    h *= 0xc4ceb9fe1a85ec53ULL;
    h ^= h >> 33;
    return h;
}

__device__ __forceinline__ void insert_edge(int s, int d) {
    s = min(max(s, 0), NN - 1);
    d = min(max(d, 0), NN - 1);
    const unsigned long long key =
        (unsigned long long)s * (unsigned long long)NN + (unsigned long long)d;
    const unsigned long long h = mix64(key);
    unsigned slot = (unsigned)h & HASH_MASK;
    unsigned fp = (unsigned)(h >> 32);
    if (fp == 0u) fp = 1u;                       // 0 is the empty sentinel

    while (true) {
        const unsigned prev = atomicCAS(&g_hash[slot], 0u, fp);
        if (prev == 0u) {                        // first occurrence of this pair
            atomicAdd(&g_in_deg[s], 1);          // REDG (return unused)
            atomicAdd(&g_out_deg[d], 1);
            return;
        }
        if (prev == fp) return;                  // duplicate — drop
        slot = (slot + 1) & HASH_MASK;
    }
}

__global__ void edge_kernel(const int* __restrict__ edge_index, int n_edges) {
    const int t = blockIdx.x * blockDim.x + threadIdx.x;
    const int e = t * 2;
    if (e + 1 < n_edges) {
        const int2 ss = *reinterpret_cast<const int2*>(edge_index + e);
        const int2 dd = *reinterpret_cast<const int2*>(edge_index + n_edges + e);
        insert_edge(ss.x, dd.x);
        insert_edge(ss.y, dd.y);
    } else if (e < n_edges) {
        insert_edge(edge_index[e], edge_index[n_edges + e]);
    }
}

// ---------------------------------------------------------------------------
// Kernel 3: node_feature = x + in_tbl[in_deg] + out_tbl[out_deg]
// Table row 0 is all-zero in the reference, so padding_idx=0 is free.
// One thread per float4 (64 per node). Threads past the feature region
// zero the (tiny) attn_bias tail of d_out — no separate launch.
// ---------------------------------------------------------------------------
__global__ void fuse_kernel(const float4* __restrict__ x,
                            const float4* __restrict__ in_tbl,
                            const float4* __restrict__ out_tbl,
                            float4* __restrict__ out,
                            long long out_elems) {
    const unsigned tid = blockIdx.x * blockDim.x + threadIdx.x;
    const unsigned total4 = (unsigned)NN * DIM4;    // 6,400,000

    if (tid < total4) {
        const unsigned node = tid >> 6;             // /64
        const unsigned col  = tid & 63;

        int di = g_in_deg[node];                    // warp-broadcast loads
        int dd = g_out_deg[node];
        di = min(max(di, 0), 511);
        dd = min(max(dd, 0), 511);

        const float4 xv = x[tid];
        const float4 a  = __ldg(&in_tbl[(unsigned)di * DIM4 + col]);
        const float4 b  = __ldg(&out_tbl[(unsigned)dd * DIM4 + col]);

        float4 r;
        r.x = xv.x + a.x + b.x;
        r.y = xv.y + a.y + b.y;
        r.z = xv.z + a.z + b.z;
        r.w = xv.w + a.w + b.w;
        out[tid] = r;
    } else {
        // tail zeroing: scalar floats beyond the node_feature region
        const long long base = (long long)NN * DIM;             // 25,600,000
        const long long i = base + (long long)(tid - total4);
        if (i < out_elems) reinterpret_cast<float*>(out)[i] = 0.0f;
    }
}

// ---------------------------------------------------------------------------
// Launch
// Inputs (metadata order):
//   0: x                 [100000, 256] float32
//   1: edge_feature      [1600000, 128] float32 (zeros — unused)
//   2: edge_index        [2, 1600000] int32 (JAX x64 disabled)
//   3: in_degree_table   [512, 256] float32
//   4: out_degree_table  [512, 256] float32
// Output: node_feature   [100000, 256] float32 (+ possible attn_bias tail)
// ---------------------------------------------------------------------------
extern "C" void kernel_launch(void* const* d_in, const int* in_sizes, int n_in,
                              void* d_out, int out_size) {
    const float4* x        = (const float4*)d_in[0];
    const int* ei          = (const int*)d_in[2];
    const float4* in_tbl   = (const float4*)d_in[3];
    const float4* out_tbl  = (const float4*)d_in[4];
    float4* out            = (float4*)d_out;

    const int n_edges = in_sizes[2] / 2;

    // 1) clear scratch (16.8 MB)
    clear_kernel<<<2048, 256>>>();

    // 2) dedup + degree count (2 edges per thread)
    const int n_thr = (n_edges + 1) / 2;
    edge_kernel<<<(n_thr + 255) / 256, 256>>>(ei, n_edges);

    // 3) fused gather-add + tail zero (HBM-bound streaming kernel)
    const long long nf_elems = (long long)NN * DIM;          // 25,600,000
    const unsigned total4 = (unsigned)NN * DIM4;             // 6,400,000
    long long extra = (long long)out_size - nf_elems;
    if (extra < 0) extra = 0;
    const unsigned total_thr = total4 + (unsigned)extra;
    fuse_kernel<<<(total_thr + 255) / 256, 256>>>(x, in_tbl, out_tbl, out,
                                                  (long long)out_size);
}